// round 6
// baseline (speedup 1.0000x reference)
#include <cuda_runtime.h>
#include <cuda_bf16.h>
#include <math.h>
#include <stdint.h>

#define BB 16
#define LSEQ 1536
#define DIM 512
#define DFF 2048
#define MROWS (BB*LSEQ)   // 24576
#define TOPK 7

typedef __nv_bfloat16 bf16;

// ------------------------- scratch (__device__ globals) -------------------------
__device__ float g_V [MROWS*DIM];
__device__ float g_T1[MROWS*DIM];
__device__ float g_T2[MROWS*DIM];
__device__ float g_T3[MROWS*DIM];
__device__ float g_T4[MROWS*DIM];
__device__ float g_MV[ BB*LSEQ ];
__device__ float g_WTS[ BB*8 ];
__device__ int   g_IDX[ 8 ];

__device__ bf16 g_XSh[MROWS*DIM], g_XSl[MROWS*DIM];
__device__ bf16 g_XWh[MROWS*DIM], g_XWl[MROWS*DIM];
__device__ bf16 g_Qh [MROWS*DIM], g_Ql [MROWS*DIM];
__device__ bf16 g_Kh [MROWS*DIM], g_Kl [MROWS*DIM];
__device__ bf16 g_Oh [MROWS*DIM], g_Ol [MROWS*DIM];
__device__ bf16 g_T1h[MROWS*DIM], g_T1l[MROWS*DIM];
__device__ bf16 g_T2h[MROWS*DIM], g_T2l[MROWS*DIM];
__device__ bf16 g_T4h[MROWS*DIM], g_T4l[MROWS*DIM];
__device__ bf16 g_FFh[(long long)MROWS*DFF], g_FFl[(long long)MROWS*DFF];
__device__ bf16 g_ICh[(long long)MROWS*3*DIM], g_ICl[(long long)MROWS*3*DIM];
__device__ bf16 g_WBh[4*DIM*DIM], g_WBl[4*DIM*DIM];
__device__ bf16 g_WTh[DIM*3*DIM], g_WTl[DIM*3*DIM];

// ------------------------- small helpers -------------------------
__device__ __forceinline__ uint32_t smem_u32(const void* p) {
    uint32_t a;
    asm("{ .reg .u64 t; cvta.to.shared.u64 t, %1; cvt.u32.u64 %0, t; }" : "=r"(a) : "l"(p));
    return a;
}
__device__ __forceinline__ void cp16(uint32_t dst, const void* src) {
    asm volatile("cp.async.cg.shared.global [%0], [%1], 16;" :: "r"(dst), "l"(src));
}
__device__ __forceinline__ void ldsm_x4(uint32_t* r, uint32_t addr) {
    asm volatile("ldmatrix.sync.aligned.m8n8.x4.shared.b16 {%0,%1,%2,%3}, [%4];"
                 : "=r"(r[0]), "=r"(r[1]), "=r"(r[2]), "=r"(r[3]) : "r"(addr));
}
__device__ __forceinline__ void mma16816(float* d, const uint32_t* a, const uint32_t* b) {
    asm volatile("mma.sync.aligned.m16n8k16.row.col.f32.bf16.bf16.f32 "
                 "{%0,%1,%2,%3}, {%4,%5,%6,%7}, {%8,%9}, {%0,%1,%2,%3};"
                 : "+f"(d[0]), "+f"(d[1]), "+f"(d[2]), "+f"(d[3])
                 : "r"(a[0]), "r"(a[1]), "r"(a[2]), "r"(a[3]), "r"(b[0]), "r"(b[1]));
}
// split fp32 pair -> (hi bf16x2, lo bf16x2) packed as uint32
__device__ __forceinline__ void split2(float x, float y, uint32_t& h, uint32_t& l) {
    __nv_bfloat162 hh = __floats2bfloat162_rn(x, y);
    h = *(const uint32_t*)&hh;
    float lx = x - __uint_as_float(h << 16);
    float ly = y - __uint_as_float(h & 0xffff0000u);
    __nv_bfloat162 ll = __floats2bfloat162_rn(lx, ly);
    l = *(const uint32_t*)&ll;
}

// ======================= bf16 hi/lo HMMA GEMM =======================
// C = A @ B^T with A,B given as bf16 hi/lo planes [rows, K] row-major.
// CTA tile 256x128, 256 threads (8 warps 4x2, 64x64 warp tiles), BK=32, 2-stage.
// flags: 1=relu, 2=+resid, 4=gram->MV, 8=write Ch/Cl, 16=write C fp32
#define RS 80
#define APL (256*RS)          // A plane: 20480
#define BPL (128*RS)          // B plane: 10240
#define STAGE (2*APL+2*BPL)   // Ahi|Alo|Bhi|Blo = 61440
#define DYN_SMEM (2*STAGE)    // 122880

__device__ __forceinline__ void issue_stage(uint32_t sbase,
    const bf16* __restrict__ Ah, const bf16* __restrict__ Al,
    const bf16* __restrict__ Bh, const bf16* __restrict__ Bl,
    int K, int m0, int n0, int k0, int tid)
{
    // A planes: 2 * 256 rows * 4 x 16B = 2048 cp16
    #pragma unroll
    for (int i = 0; i < 8; i++) {
        int id = i*256 + tid;                 // 0..2047
        int plane = id >> 10;                 // 0..1
        int rem = id & 1023;
        int row = rem >> 2, c = rem & 3;
        const bf16* pl = plane ? Al : Ah;
        const bf16* src = pl + (long long)(m0 + row)*K + k0 + c*8;
        cp16(sbase + plane*APL + row*RS + c*16, src);
    }
    // B planes: 2 * 128 rows * 4 = 1024 cp16
    #pragma unroll
    for (int i = 0; i < 4; i++) {
        int id = i*256 + tid;                 // 0..1023
        int plane = id >> 9;                  // 0..1
        int rem = id & 511;
        int row = rem >> 2, c = rem & 3;
        const bf16* pl = plane ? Bl : Bh;
        const bf16* src = pl + (long long)(n0 + row)*K + k0 + c*8;
        cp16(sbase + 2*APL + plane*BPL + row*RS + c*16, src);
    }
}

__global__ void __launch_bounds__(256, 1) gemm_bf16_kernel(
    const bf16* __restrict__ Ah, const bf16* __restrict__ Al,
    const bf16* __restrict__ Bh, const bf16* __restrict__ Bl,
    const float* __restrict__ bias, const float* __restrict__ resid,
    float* __restrict__ C, bf16* __restrict__ Ch, bf16* __restrict__ Cl,
    float* __restrict__ MV,
    int M, int N, int K, long long sA, long long sB, int flags)
{
    extern __shared__ char smem[];
    uint32_t sb = smem_u32(smem);
    int tid = threadIdx.x, lane = tid & 31, w = tid >> 5;
    int wm = w >> 1, wn = w & 1;      // 4x2 warp grid, 64x64 tiles
    long long bz = blockIdx.z;
    Ah += bz * sA; Al += bz * sA;
    Bh += bz * sB; Bl += bz * sB;
    int n0 = blockIdx.x * 128, m0 = blockIdx.y * 256;

    uint32_t aOff = (uint32_t)((wm*64 + (lane & 15))*RS + (lane >> 4)*16);
    uint32_t bOff = (uint32_t)(2*APL + (wn*64 + (lane & 15))*RS + (lane >> 4)*16);

    float acc[4][8][4];
    #pragma unroll
    for (int i = 0; i < 4; i++)
        #pragma unroll
        for (int j = 0; j < 8; j++)
            #pragma unroll
            for (int r = 0; r < 4; r++) acc[i][j][r] = 0.f;

    const int nch = K / 32;

    issue_stage(sb, Ah, Al, Bh, Bl, K, m0, n0, 0, tid);
    asm volatile("cp.async.commit_group;");

    for (int ch = 0; ch < nch; ch++) {
        asm volatile("cp.async.wait_group 0;");
        __syncthreads();
        if (ch + 1 < nch) {
            issue_stage(sb + ((ch+1) & 1)*STAGE, Ah, Al, Bh, Bl, K, m0, n0, (ch+1)*32, tid);
            asm volatile("cp.async.commit_group;");
        }

        uint32_t st = sb + (uint32_t)((ch & 1) * STAGE);
        #pragma unroll
        for (int ks = 0; ks < 2; ks++) {
            uint32_t ah[4][4], al[4][4], bh[8][2], bl[8][2];
            #pragma unroll
            for (int mt = 0; mt < 4; mt++) {
                ldsm_x4(ah[mt], st + aOff + mt*(16*RS) + ks*32);
                ldsm_x4(al[mt], st + APL + aOff + mt*(16*RS) + ks*32);
            }
            #pragma unroll
            for (int p = 0; p < 4; p++) {
                uint32_t q[4];
                ldsm_x4(q, st + bOff + p*(16*RS) + ks*32);
                bh[2*p][0] = q[0]; bh[2*p][1] = q[2];
                bh[2*p+1][0] = q[1]; bh[2*p+1][1] = q[3];
                ldsm_x4(q, st + BPL + bOff + p*(16*RS) + ks*32);
                bl[2*p][0] = q[0]; bl[2*p][1] = q[2];
                bl[2*p+1][0] = q[1]; bl[2*p+1][1] = q[3];
            }
            // term-outer ordering: same-acc MMAs spaced 32 apart
            #pragma unroll
            for (int mt = 0; mt < 4; mt++)
                #pragma unroll
                for (int nt = 0; nt < 8; nt++)
                    mma16816(acc[mt][nt], ah[mt], bh[nt]);
            #pragma unroll
            for (int mt = 0; mt < 4; mt++)
                #pragma unroll
                for (int nt = 0; nt < 8; nt++)
                    mma16816(acc[mt][nt], al[mt], bh[nt]);
            #pragma unroll
            for (int mt = 0; mt < 4; mt++)
                #pragma unroll
                for (int nt = 0; nt < 8; nt++)
                    mma16816(acc[mt][nt], ah[mt], bl[nt]);
        }
        __syncthreads();
    }

    // ------------- epilogue -------------
    if (flags & 4) {
        float* bins = (float*)smem;    // 383 wrapped diagonals of 256x128 tile
        for (int i = tid; i < 383; i += 256) bins[i] = 0.f;
        __syncthreads();
        #pragma unroll
        for (int mt = 0; mt < 4; mt++)
            #pragma unroll
            for (int nt = 0; nt < 8; nt++)
                #pragma unroll
                for (int r = 0; r < 4; r++) {
                    int ml = wm*64 + mt*16 + (lane >> 2) + ((r >> 1) & 1)*8;
                    int nl = wn*64 + nt*8 + (lane & 3)*2 + (r & 1);
                    atomicAdd(&bins[ml - nl + 127], acc[mt][nt][r]);
                }
        __syncthreads();
        for (int i = tid; i < 383; i += 256) {
            int tau = m0 - n0 - 127 + i;
            tau %= LSEQ; if (tau < 0) tau += LSEQ;
            atomicAdd(&MV[bz*LSEQ + tau], bins[i]);
        }
        return;
    }

    #pragma unroll
    for (int mt = 0; mt < 4; mt++)
        #pragma unroll
        for (int nt = 0; nt < 8; nt++) {
            int nb = n0 + wn*64 + nt*8 + (lane & 3)*2;
            #pragma unroll
            for (int h = 0; h < 2; h++) {
                int m = m0 + wm*64 + mt*16 + (lane >> 2) + h*8;
                float2 v = make_float2(acc[mt][nt][2*h], acc[mt][nt][2*h+1]);
                if (bias) { v.x += bias[nb]; v.y += bias[nb+1]; }
                if (flags & 2) {
                    float2 rr = *(const float2*)&resid[(long long)m*N + nb];
                    v.x += rr.x; v.y += rr.y;
                }
                if (flags & 1) { v.x = fmaxf(v.x, 0.f); v.y = fmaxf(v.y, 0.f); }
                if (flags & 16)
                    *(float2*)&C[(long long)m*N + nb] = v;
                if (flags & 8) {
                    uint32_t hp, lp;
                    split2(v.x, v.y, hp, lp);
                    *(uint32_t*)(Ch + (long long)m*N + nb) = hp;
                    *(uint32_t*)(Cl + (long long)m*N + nb) = lp;
                }
            }
        }
}

// ------------------------- fp32 -> hi/lo convert -------------------------
__global__ void convert_kernel(const float* __restrict__ x, bf16* __restrict__ h,
                               bf16* __restrict__ l, long long n4)
{
    long long i = (long long)blockIdx.x * blockDim.x + threadIdx.x;
    if (i >= n4) return;
    float4 v = ((const float4*)x)[i];
    uint2 hp, lp;
    split2(v.x, v.y, hp.x, lp.x);
    split2(v.z, v.w, hp.y, lp.y);
    ((uint2*)h)[i] = hp;
    ((uint2*)l)[i] = lp;
}

// ------------------------- top-7 delays + per-batch softmax weights -------------------------
__global__ void topk_kernel(const float* __restrict__ MV, int* __restrict__ idx_out,
                            float* __restrict__ w_out)
{
    __shared__ float g[LSEQ];
    __shared__ float rv[256];
    __shared__ int   ri[256];
    __shared__ int   s_idx[TOPK];
    int tid = threadIdx.x;

    for (int t = tid; t < LSEQ; t += 256) {
        float s = 0.f;
        for (int b = 0; b < BB; b++) s += MV[b*LSEQ + t];
        g[t] = s;
    }
    __syncthreads();

    for (int it = 0; it < TOPK; it++) {
        float best = -INFINITY; int bi = 0;
        for (int t = tid; t < LSEQ; t += 256)
            if (g[t] > best) { best = g[t]; bi = t; }
        rv[tid] = best; ri[tid] = bi;
        __syncthreads();
        for (int s = 128; s > 0; s >>= 1) {
            if (tid < s && rv[tid + s] > rv[tid]) { rv[tid] = rv[tid+s]; ri[tid] = ri[tid+s]; }
            __syncthreads();
        }
        if (tid == 0) { s_idx[it] = ri[0]; g[ri[0]] = -INFINITY; idx_out[it] = ri[0]; }
        __syncthreads();
    }

    if (tid < BB) {
        int b = tid;
        float wv[TOPK]; float mx = -INFINITY;
        for (int i = 0; i < TOPK; i++) {
            wv[i] = MV[b*LSEQ + s_idx[i]] * (1.0f / (float)DIM);
            mx = fmaxf(mx, wv[i]);
        }
        float s = 0.f;
        for (int i = 0; i < TOPK; i++) { wv[i] = expf(wv[i] - mx); s += wv[i]; }
        for (int i = 0; i < TOPK; i++) w_out[b*TOPK + i] = wv[i] / s;
    }
}

// ------------------------- time-delay aggregation (emit hi/lo) -------------------------
__global__ void aggregate_kernel(const float* __restrict__ V, const int* __restrict__ idx,
                                 const float* __restrict__ w,
                                 bf16* __restrict__ Oh, bf16* __restrict__ Ol)
{
    int bt = blockIdx.x;
    int b  = bt / LSEQ, t = bt % LSEQ;
    __shared__ int   s_i[TOPK];
    __shared__ float s_w[TOPK];
    if (threadIdx.x < TOPK) { s_i[threadIdx.x] = idx[threadIdx.x]; s_w[threadIdx.x] = w[b*TOPK + threadIdx.x]; }
    __syncthreads();
    int d4 = threadIdx.x;
    float4 acc = {0.f,0.f,0.f,0.f};
    #pragma unroll
    for (int i = 0; i < TOPK; i++) {
        int tt = t + s_i[i]; if (tt >= LSEQ) tt -= LSEQ;
        float4 v = *(const float4*)&V[((long long)(b*LSEQ + tt))*DIM + d4*4];
        acc.x += s_w[i]*v.x; acc.y += s_w[i]*v.y; acc.z += s_w[i]*v.z; acc.w += s_w[i]*v.w;
    }
    uint2 hp, lp;
    split2(acc.x, acc.y, hp.x, lp.x);
    split2(acc.z, acc.w, hp.y, lp.y);
    ((uint2*)(Oh + (long long)bt*DIM))[d4] = hp;
    ((uint2*)(Ol + (long long)bt*DIM))[d4] = lp;
}

// ------------------------- series_decomp (optional hi/lo) -------------------------
__global__ void decomp_kernel(const float* __restrict__ src, float* __restrict__ dst,
                              bf16* __restrict__ dh, bf16* __restrict__ dl)
{
    int d  = blockIdx.x * blockDim.x + threadIdx.x;
    int b  = blockIdx.y;
    int t0 = blockIdx.z * 128;
    long long base = (long long)b * LSEQ * DIM + d;
    const float* s = src + base;

    float sum = 0.f;
    for (int j = t0 - 12; j <= t0 + 12; j++) {
        int jc = j; if (jc < 0) jc = 0; if (jc > LSEQ-1) jc = LSEQ-1;
        sum += s[(long long)jc * DIM];
    }
    for (int t = t0; t < t0 + 128; t++) {
        float v = s[(long long)t * DIM] - sum * (1.0f/25.0f);
        dst[base + (long long)t * DIM] = v;
        if (dh) {
            bf16 hv = __float2bfloat16(v);
            dh[base + (long long)t * DIM] = hv;
            dl[base + (long long)t * DIM] = __float2bfloat16(v - __bfloat162float(hv));
        }
        int ja = t + 13; if (ja > LSEQ-1) ja = LSEQ-1;
        int jr = t - 12; if (jr < 0) jr = 0;
        sum += s[(long long)ja * DIM] - s[(long long)jr * DIM];
    }
}

// ------------------------- im2col for circular conv1d k=3 (emit hi/lo) -------------------------
__global__ void im2col_kernel(const float* __restrict__ x,
                              bf16* __restrict__ ich, bf16* __restrict__ icl)
{
    long long i = (long long)blockIdx.x * blockDim.x + threadIdx.x;
    const long long total = (long long)BB * LSEQ * 3 * (DIM/4);
    if (i >= total) return;
    int c4 = (int)(i % (DIM/4));
    long long r = i / (DIM/4);
    int j = (int)(r % 3);
    long long bt = r / 3;
    int t = (int)(bt % LSEQ);
    int b = (int)(bt / LSEQ);
    int ts = t + j - 1; if (ts < 0) ts += LSEQ; if (ts >= LSEQ) ts -= LSEQ;
    float4 v = *(const float4*)&x[((long long)(b*LSEQ + ts))*DIM + c4*4];
    uint2 hp, lp;
    split2(v.x, v.y, hp.x, lp.x);
    split2(v.z, v.w, hp.y, lp.y);
    long long o = (bt*3 + j)*DIM + (long long)c4*4;
    *(uint2*)(ich + o) = hp;
    *(uint2*)(icl + o) = lp;
}

// ------------------------- repack conv weight (O,I,3) -> [O, 3*I] hi/lo -------------------------
__global__ void repack_kernel(const float* __restrict__ W,
                              bf16* __restrict__ oh, bf16* __restrict__ ol)
{
    int i = blockIdx.x * blockDim.x + threadIdx.x;
    const int total = DIM * 3 * DIM;
    if (i >= total) return;
    int o = i / (3*DIM);
    int k = i % (3*DIM);
    int j = k / DIM, c = k % DIM;
    float v = W[((long long)o*DIM + c)*3 + j];
    bf16 hv = __float2bfloat16(v);
    oh[i] = hv;
    ol[i] = __float2bfloat16(v - __bfloat162float(hv));
}

// ------------------------- host orchestration -------------------------
static void launch_gemm(const bf16* Ah, const bf16* Al, const bf16* Bh, const bf16* Bl,
                        const float* bias, const float* resid,
                        float* C, bf16* Ch, bf16* Cl, float* MV,
                        int M, int N, int K, int batch, long long sA, long long sB, int flags)
{
    dim3 grid(N/128, M/256, batch);
    gemm_bf16_kernel<<<grid, 256, DYN_SMEM>>>(Ah, Al, Bh, Bl, bias, resid, C, Ch, Cl, MV,
                                              M, N, K, sA, sB, flags);
}

extern "C" void kernel_launch(void* const* d_in, const int* in_sizes, int n_in,
                              void* d_out, int out_size)
{
    const float* x_s      = (const float*)d_in[0];
    const float* x_w      = (const float*)d_in[1];
    const float* wc1_W    = (const float*)d_in[2];
    const float* wc1_b    = (const float*)d_in[3];
    const float* wc2_W    = (const float*)d_in[4];
    const float* wc2_b    = (const float*)d_in[5];
    const float* attn_W   = (const float*)d_in[6];
    const float* attn_b   = (const float*)d_in[7];
    const float* wc1_proj = (const float*)d_in[8];
    const float* wc2_proj = (const float*)d_in[9];
    const float* conv1_W  = (const float*)d_in[10];
    const float* conv2_W  = (const float*)d_in[11];

    float* out_res = (float*)d_out;
    float* out_xw  = out_res + (long long)MROWS * DIM;

    cudaFuncSetAttribute(gemm_bf16_kernel, cudaFuncAttributeMaxDynamicSharedMemorySize, DYN_SMEM);

    float *pV,*pT1,*pT2,*pT3,*pT4,*pMV,*pWTS;
    int* pIDX;
    cudaGetSymbolAddress((void**)&pV,  g_V);
    cudaGetSymbolAddress((void**)&pT1, g_T1);
    cudaGetSymbolAddress((void**)&pT2, g_T2);
    cudaGetSymbolAddress((void**)&pT3, g_T3);
    cudaGetSymbolAddress((void**)&pT4, g_T4);
    cudaGetSymbolAddress((void**)&pMV, g_MV);
    cudaGetSymbolAddress((void**)&pWTS,g_WTS);
    cudaGetSymbolAddress((void**)&pIDX,g_IDX);

    bf16 *pXSh,*pXSl,*pXWh,*pXWl,*pQh,*pQl,*pKh,*pKl,*pOh,*pOl;
    bf16 *pT1h,*pT1l,*pT2h,*pT2l,*pT4h,*pT4l,*pFFh,*pFFl,*pICh,*pICl,*pWBh,*pWBl,*pWTh,*pWTl;
    cudaGetSymbolAddress((void**)&pXSh, g_XSh); cudaGetSymbolAddress((void**)&pXSl, g_XSl);
    cudaGetSymbolAddress((void**)&pXWh, g_XWh); cudaGetSymbolAddress((void**)&pXWl, g_XWl);
    cudaGetSymbolAddress((void**)&pQh,  g_Qh);  cudaGetSymbolAddress((void**)&pQl,  g_Ql);
    cudaGetSymbolAddress((void**)&pKh,  g_Kh);  cudaGetSymbolAddress((void**)&pKl,  g_Kl);
    cudaGetSymbolAddress((void**)&pOh,  g_Oh);  cudaGetSymbolAddress((void**)&pOl,  g_Ol);
    cudaGetSymbolAddress((void**)&pT1h, g_T1h); cudaGetSymbolAddress((void**)&pT1l, g_T1l);
    cudaGetSymbolAddress((void**)&pT2h, g_T2h); cudaGetSymbolAddress((void**)&pT2l, g_T2l);
    cudaGetSymbolAddress((void**)&pT4h, g_T4h); cudaGetSymbolAddress((void**)&pT4l, g_T4l);
    cudaGetSymbolAddress((void**)&pFFh, g_FFh); cudaGetSymbolAddress((void**)&pFFl, g_FFl);
    cudaGetSymbolAddress((void**)&pICh, g_ICh); cudaGetSymbolAddress((void**)&pICl, g_ICl);
    cudaGetSymbolAddress((void**)&pWBh, g_WBh); cudaGetSymbolAddress((void**)&pWBl, g_WBl);
    cudaGetSymbolAddress((void**)&pWTh, g_WTh); cudaGetSymbolAddress((void**)&pWTl, g_WTl);

    const long long DD2 = (long long)DIM * DIM;
    const long long NMD = (long long)MROWS * DIM;

    auto conv = [&](const float* x, bf16* h, bf16* l, long long n) {
        long long n4 = n / 4;
        convert_kernel<<<(unsigned)((n4 + 255)/256), 256>>>(x, h, l, n4);
    };

    // run one AutoCorrelation attention given pre-split A inputs
    auto run_attn = [&](const bf16* qh, const bf16* ql, const bf16* kh, const bf16* kl,
                        const float* W, const float* bvec,
                        const float* resid, float* dest, bf16* desth, bf16* destl)
    {
        conv(W, pWBh, pWBl, 4*DD2);
        launch_gemm(qh, ql, pWBh + 0*DD2, pWBl + 0*DD2, bvec + 0*DIM, nullptr,
                    nullptr, pQh, pQl, nullptr, MROWS, DIM, DIM, 1, 0, 0, 8);
        launch_gemm(kh, kl, pWBh + 1*DD2, pWBl + 1*DD2, bvec + 1*DIM, nullptr,
                    nullptr, pKh, pKl, nullptr, MROWS, DIM, DIM, 1, 0, 0, 8);
        launch_gemm(kh, kl, pWBh + 2*DD2, pWBl + 2*DD2, bvec + 2*DIM, nullptr,
                    pV, nullptr, nullptr, nullptr, MROWS, DIM, DIM, 1, 0, 0, 16);
        cudaMemsetAsync(pMV, 0, BB*LSEQ*sizeof(float));
        launch_gemm(pQh, pQl, pKh, pKl, nullptr, nullptr,
                    nullptr, nullptr, nullptr, pMV, LSEQ, LSEQ, DIM, BB,
                    (long long)LSEQ*DIM, (long long)LSEQ*DIM, 4);
        topk_kernel<<<1, 256>>>(pMV, pIDX, pWTS);
        aggregate_kernel<<<MROWS, 128>>>(pV, pIDX, pWTS, pOh, pOl);
        int fl = 2 | (desth ? 8 : 0) | (dest ? 16 : 0);
        launch_gemm(pOh, pOl, pWBh + 3*DD2, pWBl + 3*DD2, bvec + 3*DIM, resid,
                    dest, desth, destl, nullptr, MROWS, DIM, DIM, 1, 0, 0, fl);
    };

    auto run_embed = [&](const float* x, const float* Wproj,
                         float* dest, bf16* desth, bf16* destl)
    {
        repack_kernel<<<(DIM*3*DIM + 255)/256, 256>>>(Wproj, pWTh, pWTl);
        im2col_kernel<<<(unsigned)(((long long)BB*LSEQ*3*(DIM/4) + 255)/256), 256>>>(x, pICh, pICl);
        int fl = (desth ? 8 : 0) | (dest ? 16 : 0);
        launch_gemm(pICh, pICl, pWTh, pWTl, nullptr, nullptr,
                    dest, desth, destl, nullptr, MROWS, DIM, 3*DIM, 1, 0, 0, fl);
    };

    // split harness inputs
    conv(x_s, pXSh, pXSl, NMD);
    conv(x_w, pXWh, pXWl, NMD);

    // 1) x_s1 = x_s + attn(q=x_w, k=v=x_s ; wc1)  -> T1 (fp32 + hi/lo)
    run_attn(pXWh, pXWl, pXSh, pXSl, wc1_W, wc1_b, x_s, pT1, pT1h, pT1l);
    // 2) x_w1 = token_embed(x_w, wc1_proj)        -> T2 (fp32 + hi/lo)
    run_embed(x_w, wc1_proj, pT2, pT2h, pT2l);
    // 3) x_s2 = x_s1 + attn(x_s1 ; attn_W)        -> T3 (fp32)
    run_attn(pT1h, pT1l, pT1h, pT1l, attn_W, attn_b, pT1, pT3, nullptr, nullptr);
    // 4) x_s3 = decomp(x_s2)                      -> T4 (fp32 + hi/lo)
    decomp_kernel<<<dim3(DIM/128, BB, LSEQ/128), 128>>>(pT3, pT4, pT4h, pT4l);
    // 5) x_s4 = x_s3 + attn(q=x_w1, k=v=x_s3 ; wc2) -> T1 (fp32 + hi/lo)
    run_attn(pT2h, pT2l, pT4h, pT4l, wc2_W, wc2_b, pT4, pT1, pT1h, pT1l);
    // 6) x_w_new = token_embed(x_w1, wc2_proj)    -> out_xw (fp32)
    run_embed(pT2, wc2_proj, out_xw, nullptr, nullptr);
    // 7) FFN
    conv(conv1_W, pWBh, pWBl, (long long)DFF*DIM);
    launch_gemm(pT1h, pT1l, pWBh, pWBl, nullptr, nullptr,
                nullptr, pFFh, pFFl, nullptr, MROWS, DFF, DIM, 1, 0, 0, 1 | 8);
    conv(conv2_W, pWBh, pWBl, (long long)DIM*DFF);
    launch_gemm(pFFh, pFFl, pWBh, pWBl, nullptr, pT1,
                pT3, nullptr, nullptr, nullptr, MROWS, DIM, DFF, 1, 0, 0, 2 | 16);
    // 8) res = decomp(tmp) -> out_res
    decomp_kernel<<<dim3(DIM/128, BB, LSEQ/128), 128>>>(pT3, out_res, nullptr, nullptr);
}

// round 10
// speedup vs baseline: 1.2117x; 1.2117x over previous
#include <cuda_runtime.h>
#include <cuda_bf16.h>
#include <math.h>
#include <stdint.h>

#define BB 16
#define LSEQ 1536
#define DIM 512
#define DFF 2048
#define MROWS (BB*LSEQ)   // 24576
#define TOPK 7

typedef __nv_bfloat16 bf16;

// ------------------------- scratch (__device__ globals) -------------------------
__device__ float g_V [MROWS*DIM];
__device__ float g_Qf[MROWS*DIM];
__device__ float g_Kf[MROWS*DIM];
__device__ float g_T1[MROWS*DIM];
__device__ float g_T2[MROWS*DIM];
__device__ float g_T3[MROWS*DIM];
__device__ float g_T4[MROWS*DIM];
__device__ float g_MV[ BB*LSEQ ];
__device__ float g_SP[ BB*LSEQ*2 ];     // accumulated cross-spectrum (complex)
__device__ float g_WTS[ BB*8 ];
__device__ int   g_IDX[ 8 ];

__device__ bf16 g_XSh[MROWS*DIM], g_XSl[MROWS*DIM];
__device__ bf16 g_XWh[MROWS*DIM], g_XWl[MROWS*DIM];
__device__ bf16 g_Oh [MROWS*DIM], g_Ol [MROWS*DIM];
__device__ bf16 g_T1h[MROWS*DIM], g_T1l[MROWS*DIM];
__device__ bf16 g_T2h[MROWS*DIM], g_T2l[MROWS*DIM];
__device__ bf16 g_T4h[MROWS*DIM], g_T4l[MROWS*DIM];
__device__ bf16 g_FFh[(long long)MROWS*DFF], g_FFl[(long long)MROWS*DFF];
__device__ bf16 g_ICh[(long long)MROWS*3*DIM], g_ICl[(long long)MROWS*3*DIM];
__device__ bf16 g_WBh[4*DIM*DIM], g_WBl[4*DIM*DIM];
__device__ bf16 g_WTh[DIM*3*DIM], g_WTl[DIM*3*DIM];

// ------------------------- small helpers -------------------------
__device__ __forceinline__ uint32_t smem_u32(const void* p) {
    uint32_t a;
    asm("{ .reg .u64 t; cvta.to.shared.u64 t, %1; cvt.u32.u64 %0, t; }" : "=r"(a) : "l"(p));
    return a;
}
__device__ __forceinline__ void cp16(uint32_t dst, const void* src) {
    asm volatile("cp.async.cg.shared.global [%0], [%1], 16;" :: "r"(dst), "l"(src));
}
__device__ __forceinline__ void ldsm_x4(uint32_t* r, uint32_t addr) {
    asm volatile("ldmatrix.sync.aligned.m8n8.x4.shared.b16 {%0,%1,%2,%3}, [%4];"
                 : "=r"(r[0]), "=r"(r[1]), "=r"(r[2]), "=r"(r[3]) : "r"(addr));
}
__device__ __forceinline__ void mma16816(float* d, const uint32_t* a, const uint32_t* b) {
    asm volatile("mma.sync.aligned.m16n8k16.row.col.f32.bf16.bf16.f32 "
                 "{%0,%1,%2,%3}, {%4,%5,%6,%7}, {%8,%9}, {%0,%1,%2,%3};"
                 : "+f"(d[0]), "+f"(d[1]), "+f"(d[2]), "+f"(d[3])
                 : "r"(a[0]), "r"(a[1]), "r"(a[2]), "r"(a[3]), "r"(b[0]), "r"(b[1]));
}
__device__ __forceinline__ void split2(float x, float y, uint32_t& h, uint32_t& l) {
    __nv_bfloat162 hh = __floats2bfloat162_rn(x, y);
    h = *(const uint32_t*)&hh;
    float lx = x - __uint_as_float(h << 16);
    float ly = y - __uint_as_float(h & 0xffff0000u);
    __nv_bfloat162 ll = __floats2bfloat162_rn(lx, ly);
    l = *(const uint32_t*)&ll;
}

// ======================= bf16 hi/lo HMMA GEMM (round-5 best shape) =======================
// CTA 128x128, 128 threads (4 warps, 64x64 warp tiles), BK=32, 2-stage cp.async.
// flags: 1=relu, 2=+resid, 8=write Ch/Cl, 16=write C fp32
#define RS 80
#define PL 10240
#define STAGE (4*PL)
#define DYN_SMEM (2*STAGE)  // 81920

__device__ __forceinline__ void issue_stage(uint32_t sbase,
    const bf16* __restrict__ Ah, const bf16* __restrict__ Al,
    const bf16* __restrict__ Bh, const bf16* __restrict__ Bl,
    int K, int m0, int n0, int k0, int tid)
{
    #pragma unroll
    for (int i = 0; i < 16; i++) {
        int id = i*128 + tid;
        int plane = id >> 9;
        int rem = id & 511;
        int row = rem >> 2, c = rem & 3;
        const bf16* pl = (plane == 0) ? Ah : (plane == 1) ? Al : (plane == 2) ? Bh : Bl;
        int grow = ((plane < 2) ? m0 : n0) + row;
        const bf16* src = pl + (long long)grow*K + k0 + c*8;
        cp16(sbase + plane*PL + row*RS + c*16, src);
    }
}

__global__ void __launch_bounds__(128, 2) gemm_bf16_kernel(
    const bf16* __restrict__ Ah, const bf16* __restrict__ Al,
    const bf16* __restrict__ Bh, const bf16* __restrict__ Bl,
    const float* __restrict__ bias, const float* __restrict__ resid,
    float* __restrict__ C, bf16* __restrict__ Ch, bf16* __restrict__ Cl,
    int M, int N, int K, int flags)
{
    extern __shared__ char smem[];
    uint32_t sb = smem_u32(smem);
    int tid = threadIdx.x, lane = tid & 31, w = tid >> 5;
    int wm = w >> 1, wn = w & 1;
    int n0 = blockIdx.x * 128, m0 = blockIdx.y * 128;

    uint32_t aOff = (uint32_t)((wm*64 + (lane & 15))*RS + (lane >> 4)*16);
    uint32_t bOff = (uint32_t)(2*PL + (wn*64 + (lane & 15))*RS + (lane >> 4)*16);

    float acc[4][8][4];
    #pragma unroll
    for (int i = 0; i < 4; i++)
        #pragma unroll
        for (int j = 0; j < 8; j++)
            #pragma unroll
            for (int r = 0; r < 4; r++) acc[i][j][r] = 0.f;

    const int nch = K / 32;

    issue_stage(sb, Ah, Al, Bh, Bl, K, m0, n0, 0, tid);
    asm volatile("cp.async.commit_group;");

    for (int ch = 0; ch < nch; ch++) {
        asm volatile("cp.async.wait_group 0;");
        __syncthreads();
        if (ch + 1 < nch) {
            issue_stage(sb + ((ch+1) & 1)*STAGE, Ah, Al, Bh, Bl, K, m0, n0, (ch+1)*32, tid);
            asm volatile("cp.async.commit_group;");
        }

        uint32_t st = sb + (uint32_t)((ch & 1) * STAGE);
        #pragma unroll
        for (int ks = 0; ks < 2; ks++) {
            uint32_t ah[4][4], al[4][4], bh[8][2], bl[8][2];
            #pragma unroll
            for (int mt = 0; mt < 4; mt++) {
                ldsm_x4(ah[mt], st + aOff + mt*(16*RS) + ks*32);
                ldsm_x4(al[mt], st + PL + aOff + mt*(16*RS) + ks*32);
            }
            #pragma unroll
            for (int p = 0; p < 4; p++) {
                uint32_t q[4];
                ldsm_x4(q, st + bOff + p*(16*RS) + ks*32);
                bh[2*p][0] = q[0]; bh[2*p][1] = q[2];
                bh[2*p+1][0] = q[1]; bh[2*p+1][1] = q[3];
                ldsm_x4(q, st + PL + bOff + p*(16*RS) + ks*32);
                bl[2*p][0] = q[0]; bl[2*p][1] = q[2];
                bl[2*p+1][0] = q[1]; bl[2*p+1][1] = q[3];
            }
            #pragma unroll
            for (int mt = 0; mt < 4; mt++)
                #pragma unroll
                for (int nt = 0; nt < 8; nt++)
                    mma16816(acc[mt][nt], ah[mt], bh[nt]);
            #pragma unroll
            for (int mt = 0; mt < 4; mt++)
                #pragma unroll
                for (int nt = 0; nt < 8; nt++)
                    mma16816(acc[mt][nt], al[mt], bh[nt]);
            #pragma unroll
            for (int mt = 0; mt < 4; mt++)
                #pragma unroll
                for (int nt = 0; nt < 8; nt++)
                    mma16816(acc[mt][nt], ah[mt], bl[nt]);
        }
        __syncthreads();
    }

    #pragma unroll
    for (int mt = 0; mt < 4; mt++)
        #pragma unroll
        for (int nt = 0; nt < 8; nt++) {
            int nb = n0 + wn*64 + nt*8 + (lane & 3)*2;
            #pragma unroll
            for (int h = 0; h < 2; h++) {
                int m = m0 + wm*64 + mt*16 + (lane >> 2) + h*8;
                float2 v = make_float2(acc[mt][nt][2*h], acc[mt][nt][2*h+1]);
                if (bias) { v.x += bias[nb]; v.y += bias[nb+1]; }
                if (flags & 2) {
                    float2 rr = *(const float2*)&resid[(long long)m*N + nb];
                    v.x += rr.x; v.y += rr.y;
                }
                if (flags & 1) { v.x = fmaxf(v.x, 0.f); v.y = fmaxf(v.y, 0.f); }
                if (flags & 16)
                    *(float2*)&C[(long long)m*N + nb] = v;
                if (flags & 8) {
                    uint32_t hp, lp;
                    split2(v.x, v.y, hp, lp);
                    *(uint32_t*)(Ch + (long long)m*N + nb) = hp;
                    *(uint32_t*)(Cl + (long long)m*N + nb) = lp;
                }
            }
        }
}

// ======================= FFT-based autocorrelation =======================
// 1536 = 3 x 512: 9 Stockham radix-2 stages on 3 regions + radix-3 combine.
__device__ float2* fft1536(float2* A, float2* B, const float2* __restrict__ TW, int tid)
{
    #pragma unroll 1
    for (int s = 0; s < 9; s++) {
        int Ns = 1 << s;
        int tmul = 768 >> s;
        __syncthreads();
        #pragma unroll 1
        for (int w = tid; w < 768; w += 128) {
            int reg = w >> 8;
            int j = w & 255;
            float2* src = A + (reg << 9);
            float2* dst = B + (reg << 9);
            float2 v0 = src[j];
            float2 v1 = src[j + 256];
            int jm = j & (Ns - 1);
            float2 tw = TW[jm * tmul];
            float2 t1 = make_float2(v1.x*tw.x - v1.y*tw.y, v1.x*tw.y + v1.y*tw.x);
            int idxD = ((j >> s) << (s+1)) | jm;
            dst[idxD]      = make_float2(v0.x + t1.x, v0.y + t1.y);
            dst[idxD + Ns] = make_float2(v0.x - t1.x, v0.y - t1.y);
        }
        float2* t = A; A = B; B = t;
    }
    __syncthreads();
    #pragma unroll 1
    for (int k = tid; k < 1536; k += 128) {
        int kh = k & 511;
        float2 u0 = A[kh], u1 = A[512 + kh], u2 = A[1024 + kh];
        int k2 = 2*k; if (k2 >= 1536) k2 -= 1536;    // FIX: 1536 is not pow2
        float2 t1 = TW[k];
        float2 t2 = TW[k2];
        float2 a  = make_float2(u1.x*t1.x - u1.y*t1.y, u1.x*t1.y + u1.y*t1.x);
        float2 c2 = make_float2(u2.x*t2.x - u2.y*t2.y, u2.x*t2.y + u2.y*t2.x);
        B[k] = make_float2(u0.x + a.x + c2.x, u0.y + a.y + c2.y);
    }
    __syncthreads();
    return B;
}

// forward cross-spectrum: block (g, b) handles channels g*8 .. g*8+7 (4 complex pairs)
#define FFT_SMEM (11*1536*8)   // 135168 B

__global__ void __launch_bounds__(128, 1) fft_cross_kernel(
    const float* __restrict__ Q, const float* __restrict__ K, float* __restrict__ Sg)
{
    extern __shared__ float2 sm[];
    float2* qb   = sm;            // 4*1536
    float2* kb   = sm + 4*1536;
    float2* scr  = sm + 8*1536;
    float2* Sacc = sm + 9*1536;
    float2* TW   = sm + 10*1536;
    int g = blockIdx.x, b = blockIdx.y, tid = threadIdx.x;

    for (int t = tid; t < 1536; t += 128) {
        float sn, cs;
        sincospif(-(float)t / 768.0f, &sn, &cs);
        TW[t] = make_float2(cs, sn);
        Sacc[t] = make_float2(0.f, 0.f);
    }

    const float* Qb = Q + (long long)b*LSEQ*DIM + g*8;
    const float* Kb = K + (long long)b*LSEQ*DIM + g*8;
    for (int it = tid; it < 3072; it += 128) {
        int row = it >> 1, c = it & 1;
        int pos = (row % 3)*512 + row/3;
        float4 v = *(const float4*)(Qb + (long long)row*DIM + c*4);
        qb[(2*c  )*1536 + pos] = make_float2(v.x, v.y);
        qb[(2*c+1)*1536 + pos] = make_float2(v.z, v.w);
        float4 u = *(const float4*)(Kb + (long long)row*DIM + c*4);
        kb[(2*c  )*1536 + pos] = make_float2(u.x, u.y);
        kb[(2*c+1)*1536 + pos] = make_float2(u.z, u.w);
    }

    #pragma unroll 1
    for (int p = 0; p < 4; p++) {
        float2* Qf = fft1536(qb + p*1536, scr, TW, tid);
        float2* Kf = fft1536(kb + p*1536, scr, TW, tid);
        #pragma unroll 1
        for (int k = tid; k < 1536; k += 128) {
            int km = k ? 1536 - k : 0;                // FIX: not &1535
            float2 zq = Qf[k], zqm = Qf[km], zk = Kf[k], zkm = Kf[km];
            float2 aq = make_float2(0.5f*(zq.x + zqm.x), 0.5f*(zq.y - zqm.y));
            float2 bq = make_float2(0.5f*(zq.y + zqm.y), 0.5f*(zqm.x - zq.x));
            float2 ak = make_float2(0.5f*(zk.x + zkm.x), 0.5f*(zk.y - zkm.y));
            float2 bk = make_float2(0.5f*(zk.y + zkm.y), 0.5f*(zkm.x - zk.x));
            float sx = aq.x*ak.x + aq.y*ak.y + bq.x*bk.x + bq.y*bk.y;
            float sy = aq.y*ak.x - aq.x*ak.y + bq.y*bk.x - bq.x*bk.y;
            Sacc[k].x += sx; Sacc[k].y += sy;
        }
    }
    __syncthreads();
    for (int k = tid; k < 1536; k += 128) {
        atomicAdd(&Sg[((long long)b*LSEQ + k)*2    ], Sacc[k].x);
        atomicAdd(&Sg[((long long)b*LSEQ + k)*2 + 1], Sacc[k].y);
    }
}

// inverse: MV[b][tau] = Re(iDFT(S_b))[tau] = Re(DFT(conj(S_b)))[tau] / 1536
__global__ void __launch_bounds__(128, 1) ifft_mv_kernel(
    const float* __restrict__ Sg, float* __restrict__ MV)
{
    __shared__ float2 A[1536], B[1536], TW[1536];
    int b = blockIdx.x, tid = threadIdx.x;
    for (int t = tid; t < 1536; t += 128) {
        float sn, cs;
        sincospif(-(float)t / 768.0f, &sn, &cs);
        TW[t] = make_float2(cs, sn);
    }
    for (int n = tid; n < 1536; n += 128) {
        int pos = (n % 3)*512 + n/3;
        A[pos] = make_float2(Sg[((long long)b*LSEQ + n)*2], -Sg[((long long)b*LSEQ + n)*2 + 1]);
    }
    float2* R = fft1536(A, B, TW, tid);
    for (int t = tid; t < 1536; t += 128)
        MV[b*LSEQ + t] = R[t].x * (1.0f/1536.0f);
}

// ------------------------- fp32 -> hi/lo convert -------------------------
__global__ void convert_kernel(const float* __restrict__ x, bf16* __restrict__ h,
                               bf16* __restrict__ l, long long n4)
{
    long long i = (long long)blockIdx.x * blockDim.x + threadIdx.x;
    if (i >= n4) return;
    float4 v = ((const float4*)x)[i];
    uint2 hp, lp;
    split2(v.x, v.y, hp.x, lp.x);
    split2(v.z, v.w, hp.y, lp.y);
    ((uint2*)h)[i] = hp;
    ((uint2*)l)[i] = lp;
}

// ------------------------- top-7 delays + per-batch softmax weights -------------------------
__global__ void topk_kernel(const float* __restrict__ MV, int* __restrict__ idx_out,
                            float* __restrict__ w_out)
{
    __shared__ float g[LSEQ];
    __shared__ float rv[256];
    __shared__ int   ri[256];
    __shared__ int   s_idx[TOPK];
    int tid = threadIdx.x;

    for (int t = tid; t < LSEQ; t += 256) {
        float s = 0.f;
        for (int b = 0; b < BB; b++) s += MV[b*LSEQ + t];
        g[t] = s;
    }
    __syncthreads();

    for (int it = 0; it < TOPK; it++) {
        float best = -INFINITY; int bi = 0;
        for (int t = tid; t < LSEQ; t += 256)
            if (g[t] > best) { best = g[t]; bi = t; }
        rv[tid] = best; ri[tid] = bi;
        __syncthreads();
        for (int s = 128; s > 0; s >>= 1) {
            if (tid < s && rv[tid + s] > rv[tid]) { rv[tid] = rv[tid+s]; ri[tid] = ri[tid+s]; }
            __syncthreads();
        }
        if (tid == 0) { s_idx[it] = ri[0]; g[ri[0]] = -INFINITY; idx_out[it] = ri[0]; }
        __syncthreads();
    }

    if (tid < BB) {
        int b = tid;
        float wv[TOPK]; float mx = -INFINITY;
        for (int i = 0; i < TOPK; i++) {
            wv[i] = MV[b*LSEQ + s_idx[i]] * (1.0f / (float)DIM);
            mx = fmaxf(mx, wv[i]);
        }
        float s = 0.f;
        for (int i = 0; i < TOPK; i++) { wv[i] = expf(wv[i] - mx); s += wv[i]; }
        for (int i = 0; i < TOPK; i++) w_out[b*TOPK + i] = wv[i] / s;
    }
}

// ------------------------- time-delay aggregation (emit hi/lo) -------------------------
__global__ void aggregate_kernel(const float* __restrict__ V, const int* __restrict__ idx,
                                 const float* __restrict__ w,
                                 bf16* __restrict__ Oh, bf16* __restrict__ Ol)
{
    int bt = blockIdx.x;
    int b  = bt / LSEQ, t = bt % LSEQ;
    __shared__ int   s_i[TOPK];
    __shared__ float s_w[TOPK];
    if (threadIdx.x < TOPK) { s_i[threadIdx.x] = idx[threadIdx.x]; s_w[threadIdx.x] = w[b*TOPK + threadIdx.x]; }
    __syncthreads();
    int d4 = threadIdx.x;
    float4 acc = {0.f,0.f,0.f,0.f};
    #pragma unroll
    for (int i = 0; i < TOPK; i++) {
        int tt = t + s_i[i]; if (tt >= LSEQ) tt -= LSEQ;
        float4 v = *(const float4*)&V[((long long)(b*LSEQ + tt))*DIM + d4*4];
        acc.x += s_w[i]*v.x; acc.y += s_w[i]*v.y; acc.z += s_w[i]*v.z; acc.w += s_w[i]*v.w;
    }
    uint2 hp, lp;
    split2(acc.x, acc.y, hp.x, lp.x);
    split2(acc.z, acc.w, hp.y, lp.y);
    ((uint2*)(Oh + (long long)bt*DIM))[d4] = hp;
    ((uint2*)(Ol + (long long)bt*DIM))[d4] = lp;
}

// ------------------------- series_decomp (optional hi/lo) -------------------------
__global__ void decomp_kernel(const float* __restrict__ src, float* __restrict__ dst,
                              bf16* __restrict__ dh, bf16* __restrict__ dl)
{
    int d  = blockIdx.x * blockDim.x + threadIdx.x;
    int b  = blockIdx.y;
    int t0 = blockIdx.z * 128;
    long long base = (long long)b * LSEQ * DIM + d;
    const float* s = src + base;

    float sum = 0.f;
    for (int j = t0 - 12; j <= t0 + 12; j++) {
        int jc = j; if (jc < 0) jc = 0; if (jc > LSEQ-1) jc = LSEQ-1;
        sum += s[(long long)jc * DIM];
    }
    for (int t = t0; t < t0 + 128; t++) {
        float v = s[(long long)t * DIM] - sum * (1.0f/25.0f);
        dst[base + (long long)t * DIM] = v;
        if (dh) {
            bf16 hv = __float2bfloat16(v);
            dh[base + (long long)t * DIM] = hv;
            dl[base + (long long)t * DIM] = __float2bfloat16(v - __bfloat162float(hv));
        }
        int ja = t + 13; if (ja > LSEQ-1) ja = LSEQ-1;
        int jr = t - 12; if (jr < 0) jr = 0;
        sum += s[(long long)ja * DIM] - s[(long long)jr * DIM];
    }
}

// ------------------------- im2col for circular conv1d k=3 (emit hi/lo) -------------------------
__global__ void im2col_kernel(const float* __restrict__ x,
                              bf16* __restrict__ ich, bf16* __restrict__ icl)
{
    long long i = (long long)blockIdx.x * blockDim.x + threadIdx.x;
    const long long total = (long long)BB * LSEQ * 3 * (DIM/4);
    if (i >= total) return;
    int c4 = (int)(i % (DIM/4));
    long long r = i / (DIM/4);
    int j = (int)(r % 3);
    long long bt = r / 3;
    int t = (int)(bt % LSEQ);
    int b = (int)(bt / LSEQ);
    int ts = t + j - 1; if (ts < 0) ts += LSEQ; if (ts >= LSEQ) ts -= LSEQ;
    float4 v = *(const float4*)&x[((long long)(b*LSEQ + ts))*DIM + c4*4];
    uint2 hp, lp;
    split2(v.x, v.y, hp.x, lp.x);
    split2(v.z, v.w, hp.y, lp.y);
    long long o = (bt*3 + j)*DIM + (long long)c4*4;
    *(uint2*)(ich + o) = hp;
    *(uint2*)(icl + o) = lp;
}

// ------------------------- repack conv weight (O,I,3) -> [O, 3*I] hi/lo -------------------------
__global__ void repack_kernel(const float* __restrict__ W,
                              bf16* __restrict__ oh, bf16* __restrict__ ol)
{
    int i = blockIdx.x * blockDim.x + threadIdx.x;
    const int total = DIM * 3 * DIM;
    if (i >= total) return;
    int o = i / (3*DIM);
    int k = i % (3*DIM);
    int j = k / DIM, c = k % DIM;
    float v = W[((long long)o*DIM + c)*3 + j];
    bf16 hv = __float2bfloat16(v);
    oh[i] = hv;
    ol[i] = __float2bfloat16(v - __bfloat162float(hv));
}

// ------------------------- host orchestration -------------------------
static void launch_gemm(const bf16* Ah, const bf16* Al, const bf16* Bh, const bf16* Bl,
                        const float* bias, const float* resid,
                        float* C, bf16* Ch, bf16* Cl,
                        int M, int N, int K, int flags)
{
    dim3 grid(N/128, M/128, 1);
    gemm_bf16_kernel<<<grid, 128, DYN_SMEM>>>(Ah, Al, Bh, Bl, bias, resid, C, Ch, Cl,
                                              M, N, K, flags);
}

extern "C" void kernel_launch(void* const* d_in, const int* in_sizes, int n_in,
                              void* d_out, int out_size)
{
    const float* x_s      = (const float*)d_in[0];
    const float* x_w      = (const float*)d_in[1];
    const float* wc1_W    = (const float*)d_in[2];
    const float* wc1_b    = (const float*)d_in[3];
    const float* wc2_W    = (const float*)d_in[4];
    const float* wc2_b    = (const float*)d_in[5];
    const float* attn_W   = (const float*)d_in[6];
    const float* attn_b   = (const float*)d_in[7];
    const float* wc1_proj = (const float*)d_in[8];
    const float* wc2_proj = (const float*)d_in[9];
    const float* conv1_W  = (const float*)d_in[10];
    const float* conv2_W  = (const float*)d_in[11];

    float* out_res = (float*)d_out;
    float* out_xw  = out_res + (long long)MROWS * DIM;

    cudaFuncSetAttribute(gemm_bf16_kernel, cudaFuncAttributeMaxDynamicSharedMemorySize, DYN_SMEM);
    cudaFuncSetAttribute(fft_cross_kernel, cudaFuncAttributeMaxDynamicSharedMemorySize, FFT_SMEM);

    float *pV,*pQf,*pKf,*pT1,*pT2,*pT3,*pT4,*pMV,*pSP,*pWTS;
    int* pIDX;
    cudaGetSymbolAddress((void**)&pV,  g_V);
    cudaGetSymbolAddress((void**)&pQf, g_Qf);
    cudaGetSymbolAddress((void**)&pKf, g_Kf);
    cudaGetSymbolAddress((void**)&pT1, g_T1);
    cudaGetSymbolAddress((void**)&pT2, g_T2);
    cudaGetSymbolAddress((void**)&pT3, g_T3);
    cudaGetSymbolAddress((void**)&pT4, g_T4);
    cudaGetSymbolAddress((void**)&pMV, g_MV);
    cudaGetSymbolAddress((void**)&pSP, g_SP);
    cudaGetSymbolAddress((void**)&pWTS,g_WTS);
    cudaGetSymbolAddress((void**)&pIDX,g_IDX);

    bf16 *pXSh,*pXSl,*pXWh,*pXWl,*pOh,*pOl;
    bf16 *pT1h,*pT1l,*pT2h,*pT2l,*pT4h,*pT4l,*pFFh,*pFFl,*pICh,*pICl,*pWBh,*pWBl,*pWTh,*pWTl;
    cudaGetSymbolAddress((void**)&pXSh, g_XSh); cudaGetSymbolAddress((void**)&pXSl, g_XSl);
    cudaGetSymbolAddress((void**)&pXWh, g_XWh); cudaGetSymbolAddress((void**)&pXWl, g_XWl);
    cudaGetSymbolAddress((void**)&pOh,  g_Oh);  cudaGetSymbolAddress((void**)&pOl,  g_Ol);
    cudaGetSymbolAddress((void**)&pT1h, g_T1h); cudaGetSymbolAddress((void**)&pT1l, g_T1l);
    cudaGetSymbolAddress((void**)&pT2h, g_T2h); cudaGetSymbolAddress((void**)&pT2l, g_T2l);
    cudaGetSymbolAddress((void**)&pT4h, g_T4h); cudaGetSymbolAddress((void**)&pT4l, g_T4l);
    cudaGetSymbolAddress((void**)&pFFh, g_FFh); cudaGetSymbolAddress((void**)&pFFl, g_FFl);
    cudaGetSymbolAddress((void**)&pICh, g_ICh); cudaGetSymbolAddress((void**)&pICl, g_ICl);
    cudaGetSymbolAddress((void**)&pWBh, g_WBh); cudaGetSymbolAddress((void**)&pWBl, g_WBl);
    cudaGetSymbolAddress((void**)&pWTh, g_WTh); cudaGetSymbolAddress((void**)&pWTl, g_WTl);

    const long long DD2 = (long long)DIM * DIM;
    const long long NMD = (long long)MROWS * DIM;

    auto conv = [&](const float* x, bf16* h, bf16* l, long long n) {
        long long n4 = n / 4;
        convert_kernel<<<(unsigned)((n4 + 255)/256), 256>>>(x, h, l, n4);
    };

    auto run_attn = [&](const bf16* qh, const bf16* ql, const bf16* kh, const bf16* kl,
                        const float* W, const float* bvec,
                        const float* resid, float* dest, bf16* desth, bf16* destl)
    {
        conv(W, pWBh, pWBl, 4*DD2);
        launch_gemm(qh, ql, pWBh + 0*DD2, pWBl + 0*DD2, bvec + 0*DIM, nullptr,
                    pQf, nullptr, nullptr, MROWS, DIM, DIM, 16);
        launch_gemm(kh, kl, pWBh + 1*DD2, pWBl + 1*DD2, bvec + 1*DIM, nullptr,
                    pKf, nullptr, nullptr, MROWS, DIM, DIM, 16);
        launch_gemm(kh, kl, pWBh + 2*DD2, pWBl + 2*DD2, bvec + 2*DIM, nullptr,
                    pV, nullptr, nullptr, MROWS, DIM, DIM, 16);
        cudaMemsetAsync(pSP, 0, BB*LSEQ*2*sizeof(float));
        fft_cross_kernel<<<dim3(64, BB), 128, FFT_SMEM>>>(pQf, pKf, pSP);
        ifft_mv_kernel<<<BB, 128>>>(pSP, pMV);
        topk_kernel<<<1, 256>>>(pMV, pIDX, pWTS);
        aggregate_kernel<<<MROWS, 128>>>(pV, pIDX, pWTS, pOh, pOl);
        int fl = 2 | (desth ? 8 : 0) | (dest ? 16 : 0);
        launch_gemm(pOh, pOl, pWBh + 3*DD2, pWBl + 3*DD2, bvec + 3*DIM, resid,
                    dest, desth, destl, MROWS, DIM, DIM, fl);
    };

    auto run_embed = [&](const float* x, const float* Wproj,
                         float* dest, bf16* desth, bf16* destl)
    {
        repack_kernel<<<(DIM*3*DIM + 255)/256, 256>>>(Wproj, pWTh, pWTl);
        im2col_kernel<<<(unsigned)(((long long)BB*LSEQ*3*(DIM/4) + 255)/256), 256>>>(x, pICh, pICl);
        int fl = (desth ? 8 : 0) | (dest ? 16 : 0);
        launch_gemm(pICh, pICl, pWTh, pWTl, nullptr, nullptr,
                    dest, desth, destl, MROWS, DIM, 3*DIM, fl);
    };

    // split harness inputs
    conv(x_s, pXSh, pXSl, NMD);
    conv(x_w, pXWh, pXWl, NMD);

    // 1) x_s1 = x_s + attn(q=x_w, k=v=x_s ; wc1)  -> T1 (fp32 + hi/lo)
    run_attn(pXWh, pXWl, pXSh, pXSl, wc1_W, wc1_b, x_s, pT1, pT1h, pT1l);
    // 2) x_w1 = token_embed(x_w, wc1_proj)        -> T2 (fp32 + hi/lo)
    run_embed(x_w, wc1_proj, pT2, pT2h, pT2l);
    // 3) x_s2 = x_s1 + attn(x_s1 ; attn_W)        -> T3 (fp32)
    run_attn(pT1h, pT1l, pT1h, pT1l, attn_W, attn_b, pT1, pT3, nullptr, nullptr);
    // 4) x_s3 = decomp(x_s2)                      -> T4 (fp32 + hi/lo)
    decomp_kernel<<<dim3(DIM/128, BB, LSEQ/128), 128>>>(pT3, pT4, pT4h, pT4l);
    // 5) x_s4 = x_s3 + attn(q=x_w1, k=v=x_s3 ; wc2) -> T1 (fp32 + hi/lo)
    run_attn(pT2h, pT2l, pT4h, pT4l, wc2_W, wc2_b, pT4, pT1, pT1h, pT1l);
    // 6) x_w_new = token_embed(x_w1, wc2_proj)    -> out_xw (fp32)
    run_embed(pT2, wc2_proj, out_xw, nullptr, nullptr);
    // 7) FFN
    conv(conv1_W, pWBh, pWBl, (long long)DFF*DIM);
    launch_gemm(pT1h, pT1l, pWBh, pWBl, nullptr, nullptr,
                nullptr, pFFh, pFFl, MROWS, DFF, DIM, 1 | 8);
    conv(conv2_W, pWBh, pWBl, (long long)DIM*DFF);
    launch_gemm(pFFh, pFFl, pWBh, pWBl, nullptr, pT1,
                pT3, nullptr, nullptr, MROWS, DIM, DFF, 2 | 16);
    // 8) res = decomp(tmp) -> out_res
    decomp_kernel<<<dim3(DIM/128, BB, LSEQ/128), 128>>>(pT3, out_res, nullptr, nullptr);
}